// round 2
// baseline (speedup 1.0000x reference)
#include <cuda_runtime.h>

#define NB 16
#define NH 16
#define NI 512
#define NE 512
#define IE (NI * NE)

// Scratch (device globals; allocations are forbidden)
__device__ float g_embp[2][NB * NH * NE];  // 1 MB: emb partials (j-split = 2)
__device__ float g_part[8][NB * NH * NE];  // 4 MB: GEMM split-K partials

// ---------------------------------------------------------------------------
// Kernel 1: emb[b,h,e] = sum_j x[b,j,e] * W_v[h,j,e]
// Block = 8 b x 8 h x 32 e x 256 j. 256 threads = 32 e-lanes x 8 j-slices.
// Each thread: 8x8 register accumulator; per j: 16 coalesced LDG + 64 FMA.
// Cross-slice reduction via smem transpose (two 32-entry halves, 32 KB).
// ---------------------------------------------------------------------------
__global__ __launch_bounds__(256) void emb_kernel(const float* __restrict__ x,
                                                  const float* __restrict__ wv) {
    const int t   = threadIdx.x;
    const int el  = t & 31;            // e lane (coalesced)
    const int sl  = t >> 5;            // j slice (warp id) 0..7
    const int bid = blockIdx.x;        // 128 blocks
    const int ec  = bid & 15;          // e chunk 0..15
    const int hg  = (bid >> 4) & 1;    // h half
    const int bg  = (bid >> 5) & 1;    // b half
    const int js  = bid >> 6;          // j split 0..1

    const int e = ec * 32 + el;
    const float* xp = x  + bg * 8 * IE + e;
    const float* wp = wv + hg * 8 * IE + e;

    float acc[8][8];
#pragma unroll
    for (int i = 0; i < 8; ++i)
#pragma unroll
        for (int k = 0; k < 8; ++k) acc[i][k] = 0.f;

    const int j0 = js * 256;
#pragma unroll 2
    for (int jj = 0; jj < 32; ++jj) {
        const int joff = (j0 + sl + jj * 8) * NE;
        float xv[8], wv8[8];
#pragma unroll
        for (int i = 0; i < 8; ++i) xv[i]  = __ldg(xp + i * IE + joff);
#pragma unroll
        for (int k = 0; k < 8; ++k) wv8[k] = __ldg(wp + k * IE + joff);
#pragma unroll
        for (int i = 0; i < 8; ++i)
#pragma unroll
            for (int k = 0; k < 8; ++k)
                acc[i][k] = fmaf(xv[i], wv8[k], acc[i][k]);
    }

    __shared__ float red[8][32][32];   // [slice][ik][el] - conflict-free both ways
    const int b0 = bg * 8, h0 = hg * 8;
#pragma unroll
    for (int half = 0; half < 2; ++half) {
        __syncthreads();
#pragma unroll
        for (int ik = 0; ik < 32; ++ik) {
            const int ikf = half * 32 + ik;
            red[sl][ik][el] = acc[ikf >> 3][ikf & 7];
        }
        __syncthreads();
#pragma unroll
        for (int r = 0; r < 4; ++r) {
            const int ik = r * 8 + sl;
            float s = 0.f;
#pragma unroll
            for (int q = 0; q < 8; ++q) s += red[q][ik][el];
            const int ikf = half * 32 + ik;
            const int b = b0 + (ikf >> 3);
            const int h = h0 + (ikf & 7);
            g_embp[js][(b * NH + h) * NE + e] = s;
        }
    }
}

// ---------------------------------------------------------------------------
// Kernel 2: split-K GEMM partials. out[m][n] = sum_k emb[m][k]*w[n][k].
// M=256, N=512, K=512. Tiles 64x64x64, K-split 8 -> 256 blocks.
// A-tile load folds the two j-split emb partials. 4x4 register micro-tiles.
// ---------------------------------------------------------------------------
__global__ __launch_bounds__(256) void gemm_kernel(const float* __restrict__ w) {
    const int t   = threadIdx.x;
    const int bid = blockIdx.x;        // 256 = 4 mt x 8 nt x 8 kt
    const int kt  = bid & 7;
    const int nt  = (bid >> 3) & 7;
    const int mt  = bid >> 6;
    const int m0 = mt * 64, n0 = nt * 64, k0 = kt * 64;

    __shared__ __align__(16) float sa[64][68];  // [k][m], stride 68: 16B row align
    __shared__ __align__(16) float sb[64][68];  // [k][n]

#pragma unroll
    for (int r = 0; r < 4; ++r) {
        const int lin = t + r * 256;        // 0..1023 float4 slots
        const int row = lin >> 4;           // 0..63
        const int kq  = (lin & 15) * 4;     // 0..60
        const float4 a0 = *(const float4*)&g_embp[0][(m0 + row) * NE + k0 + kq];
        const float4 a1 = *(const float4*)&g_embp[1][(m0 + row) * NE + k0 + kq];
        sa[kq + 0][row] = a0.x + a1.x;
        sa[kq + 1][row] = a0.y + a1.y;
        sa[kq + 2][row] = a0.z + a1.z;
        sa[kq + 3][row] = a0.w + a1.w;
        const float4 b4 = *(const float4*)&w[(n0 + row) * NE + k0 + kq];
        sb[kq + 0][row] = b4.x;
        sb[kq + 1][row] = b4.y;
        sb[kq + 2][row] = b4.z;
        sb[kq + 3][row] = b4.w;
    }
    __syncthreads();

    const int tx = t & 15;   // n micro-tile
    const int ty = t >> 4;   // m micro-tile
    float acc[4][4];
#pragma unroll
    for (int i = 0; i < 4; ++i)
#pragma unroll
        for (int j = 0; j < 4; ++j) acc[i][j] = 0.f;

#pragma unroll 8
    for (int kk = 0; kk < 64; ++kk) {
        const float4 av = *(const float4*)&sa[kk][ty * 4];
        const float4 bv = *(const float4*)&sb[kk][tx * 4];
        const float a[4] = {av.x, av.y, av.z, av.w};
        const float b[4] = {bv.x, bv.y, bv.z, bv.w};
#pragma unroll
        for (int i = 0; i < 4; ++i)
#pragma unroll
            for (int j = 0; j < 4; ++j)
                acc[i][j] = fmaf(a[i], b[j], acc[i][j]);
    }

#pragma unroll
    for (int i = 0; i < 4; ++i) {
        float4 v;
        v.x = acc[i][0]; v.y = acc[i][1]; v.z = acc[i][2]; v.w = acc[i][3];
        *(float4*)&g_part[kt][(m0 + ty * 4 + i) * NE + n0 + tx * 4] = v;
    }
}

// ---------------------------------------------------------------------------
// Kernel 3: out = sum of 8 split-K partials + bias.
// ---------------------------------------------------------------------------
__global__ __launch_bounds__(256) void finish_kernel(const float* __restrict__ bias,
                                                     float* __restrict__ out) {
    const int idx = blockIdx.x * 256 + threadIdx.x;  // float4 index, 32768 total
    const int o = idx * 4;
    float4 s = *(const float4*)&g_part[0][o];
#pragma unroll
    for (int p = 1; p < 8; ++p) {
        const float4 v = *(const float4*)&g_part[p][o];
        s.x += v.x; s.y += v.y; s.z += v.z; s.w += v.w;
    }
    const float4 bv = *(const float4*)&bias[o & (NE - 1)];
    s.x += bv.x; s.y += bv.y; s.z += bv.z; s.w += bv.w;
    *(float4*)&out[o] = s;
}

extern "C" void kernel_launch(void* const* d_in, const int* in_sizes, int n_in,
                              void* d_out, int out_size) {
    const float* x    = (const float*)d_in[0];  // [16,1,512,512]
    // d_in[1] = W_q, d_in[2] = W_k: mathematically dead (softmax cols sum to 1)
    const float* wv   = (const float*)d_in[3];  // [1,16,512,512]
    const float* mlpw = (const float*)d_in[4];  // [512,512]
    const float* mlpb = (const float*)d_in[5];  // [512]
    float* out = (float*)d_out;                 // [16,16,512]

    emb_kernel<<<128, 256>>>(x, wv);
    gemm_kernel<<<256, 256>>>(mlpw);
    finish_kernel<<<128, 256>>>(mlpb, out);
}